// round 1
// baseline (speedup 1.0000x reference)
#include <cuda_runtime.h>
#include <cuda_bf16.h>
#include <math.h>

// Problem dims (fixed by the dataset)
#define B_  32
#define N_  512
#define DIN 768
#define DOUT 256
#define H_  8
#define M_  (B_ * N_)          // 16384 rows

// ---------------- device scratch (no allocations allowed) ----------------
__device__ float g_Wh  [(size_t)H_ * M_ * DOUT];   // layer-1 per-head Wh   (134 MB)
__device__ float g_f1  [H_ * M_];
__device__ float g_f2  [H_ * M_];
__device__ float g_rm  [H_ * M_];
__device__ float g_dn  [H_ * M_];
__device__ float g_hmid[(size_t)M_ * DOUT];        // layer-1 output (mean of elu heads)
__device__ float g_Wh2 [(size_t)M_ * DOUT];
__device__ float g_f1b [M_];
__device__ float g_f2b [M_];
__device__ float g_rm2 [M_];
__device__ float g_dn2 [M_];

// ---------------- SGEMM: C[z] = A @ Bw[z], row-major, 128x128x16, 8x8/thread ----
// A: [M,K] (shared across z), Bw: [z][K,Nf], C: [z][M,Nf]
__global__ __launch_bounds__(256) void sgemm_kernel(
    const float* __restrict__ A, const float* __restrict__ Bw,
    float* __restrict__ C, int M, int K, int Nf)
{
    const float* Bh = Bw + (size_t)blockIdx.z * K * Nf;
    float* Ch       = C  + (size_t)blockIdx.z * M * Nf;
    const int m0 = blockIdx.x * 128;
    const int f0 = blockIdx.y * 128;

    __shared__ float As[16][128];
    __shared__ float Bs[16][128];

    const int t  = threadIdx.x;
    const int tx = t & 15;       // 0..15 -> 8 cols each
    const int ty = t >> 4;       // 0..15 -> 8 rows each

    float acc[8][8];
    #pragma unroll
    for (int i = 0; i < 8; ++i)
        #pragma unroll
        for (int j = 0; j < 8; ++j) acc[i][j] = 0.0f;

    for (int k0 = 0; k0 < K; k0 += 16) {
        // load A tile 128x16 (transpose into As[k][m])
        {
            int row = t >> 1;            // 0..127
            int kc  = (t & 1) * 8;       // 0 or 8
            const float* ap = &A[(size_t)(m0 + row) * K + k0 + kc];
            float4 v0 = *(const float4*)(ap);
            float4 v1 = *(const float4*)(ap + 4);
            As[kc + 0][row] = v0.x; As[kc + 1][row] = v0.y;
            As[kc + 2][row] = v0.z; As[kc + 3][row] = v0.w;
            As[kc + 4][row] = v1.x; As[kc + 5][row] = v1.y;
            As[kc + 6][row] = v1.z; As[kc + 7][row] = v1.w;
        }
        // load B tile 16x128
        {
            int j = (t & 31) * 4;
            int k = t >> 5;              // 0..7
            *(float4*)&Bs[k][j]     = *(const float4*)&Bh[(size_t)(k0 + k) * Nf + f0 + j];
            *(float4*)&Bs[k + 8][j] = *(const float4*)&Bh[(size_t)(k0 + k + 8) * Nf + f0 + j];
        }
        __syncthreads();

        #pragma unroll
        for (int k = 0; k < 16; ++k) {
            float ra[8], rb[8];
            *(float4*)&ra[0] = *(const float4*)&As[k][ty * 8];
            *(float4*)&ra[4] = *(const float4*)&As[k][ty * 8 + 4];
            *(float4*)&rb[0] = *(const float4*)&Bs[k][tx * 8];
            *(float4*)&rb[4] = *(const float4*)&Bs[k][tx * 8 + 4];
            #pragma unroll
            for (int i = 0; i < 8; ++i)
                #pragma unroll
                for (int j = 0; j < 8; ++j)
                    acc[i][j] = fmaf(ra[i], rb[j], acc[i][j]);
        }
        __syncthreads();
    }

    #pragma unroll
    for (int i = 0; i < 8; ++i) {
        size_t off = (size_t)(m0 + ty * 8 + i) * Nf + f0 + tx * 8;
        *(float4*)&Ch[off]     = *(float4*)&acc[i][0];
        *(float4*)&Ch[off + 4] = *(float4*)&acc[i][4];
    }
}

// ---------------- f1/f2: one warp per row: f = Wh[row,:] . a ------------------
__global__ __launch_bounds__(256) void f12_kernel(
    const float* __restrict__ Wh, const float* __restrict__ a1,
    const float* __restrict__ a2, float* __restrict__ f1,
    float* __restrict__ f2, int rows, int Mper)
{
    int warp = (blockIdx.x * blockDim.x + threadIdx.x) >> 5;
    int lane = threadIdx.x & 31;
    if (warp >= rows) return;
    int h = warp / Mper;
    const float* row = Wh + (size_t)warp * DOUT;
    const float* a1h = a1 + h * DOUT;
    const float* a2h = a2 + h * DOUT;
    float s1 = 0.0f, s2 = 0.0f;
    #pragma unroll
    for (int f = lane; f < DOUT; f += 32) {
        float w = row[f];
        s1 = fmaf(w, a1h[f], s1);
        s2 = fmaf(w, a2h[f], s2);
    }
    #pragma unroll
    for (int off = 16; off; off >>= 1) {
        s1 += __shfl_xor_sync(0xffffffffu, s1, off);
        s2 += __shfl_xor_sync(0xffffffffu, s2, off);
    }
    if (lane == 0) { f1[warp] = s1; f2[warp] = s2; }
}

// ---------------- row stats: masked rowmax + softmax denominator -------------
__global__ __launch_bounds__(256) void rowstats_kernel(
    const float* __restrict__ f1, const float* __restrict__ f2,
    const int* __restrict__ adj, float* __restrict__ rowmax,
    float* __restrict__ denom, int rows)
{
    int warp = (blockIdx.x * blockDim.x + threadIdx.x) >> 5;
    int lane = threadIdx.x & 31;
    if (warp >= rows) return;
    int n  = warp & (N_ - 1);
    int hb = warp >> 9;               // h*B + b
    int b  = hb & (B_ - 1);
    float f1v = f1[warp];
    const float* f2row = f2 + (size_t)hb * N_;
    const int* adjrow  = adj + ((size_t)b * N_ + n) * N_;

    float e[16];
    float mx = -1e30f;
    #pragma unroll
    for (int q = 0; q < 16; ++q) {
        int m = q * 32 + lane;
        float v = f1v + f2row[m];
        v = v > 0.0f ? v : 0.2f * v;            // LeakyReLU(0.2)
        e[q] = (adjrow[m] > 0) ? v : -1e30f;
        mx = fmaxf(mx, e[q]);
    }
    #pragma unroll
    for (int off = 16; off; off >>= 1)
        mx = fmaxf(mx, __shfl_xor_sync(0xffffffffu, mx, off));
    float s = 0.0f;
    #pragma unroll
    for (int q = 0; q < 16; ++q)
        if (e[q] > -1e29f) s += __expf(e[q] - mx);
    #pragma unroll
    for (int off = 16; off; off >>= 1)
        s += __shfl_xor_sync(0xffffffffu, s, off);
    if (lane == 0) { rowmax[warp] = mx; denom[warp] = s; }
}

// ---------------- attention aggregation: out = reduce_h( act(P_h @ Wh_h) ) ---
// Tiles: 64 rows (n) x 128 cols (f), m-tile 32. P computed on the fly.
// NHEADS=8/FINAL=false: out = (1/8) * sum_h elu(O_h)
// NHEADS=1/FINAL=true : out = relu(O)
template<int NHEADS, bool FINAL>
__global__ __launch_bounds__(256) void attn_kernel(
    const float* __restrict__ Wh,   // [NHEADS][B][N][DOUT]
    const float* __restrict__ f1,   // [NHEADS][B][N]
    const float* __restrict__ f2,
    const float* __restrict__ rowmax,
    const float* __restrict__ denom,
    const int*   __restrict__ adj,  // [B][N][N]
    float* __restrict__ out)        // [B][N][DOUT]
{
    const int b  = blockIdx.z;
    const int n0 = blockIdx.y * 64;
    const int f0 = blockIdx.x * 128;

    __shared__ float Ps[32][65];    // [m_local][n_local], padded
    __shared__ float Whs[32][128];  // [m_local][f_local]
    __shared__ float sf1[64], srm[64], sinv[64];

    const int t  = threadIdx.x;
    const int tx = t & 15;          // 8 f-cols each
    const int ty = t >> 4;          // 4 n-rows each

    float sum[4][8];
    #pragma unroll
    for (int i = 0; i < 4; ++i)
        #pragma unroll
        for (int j = 0; j < 8; ++j) sum[i][j] = 0.0f;

    for (int h = 0; h < NHEADS; ++h) {
        const size_t hb = (size_t)h * B_ + b;
        const float* Whh = Wh + hb * N_ * DOUT;
        const float* f2h = f2 + hb * N_;
        if (t < 64) {
            sf1[t] = f1[hb * N_ + n0 + t];
            srm[t] = rowmax[hb * N_ + n0 + t];
            float d = denom[hb * N_ + n0 + t];
            sinv[t] = d > 0.0f ? 1.0f / d : 0.0f;
        }
        float acc[4][8];
        #pragma unroll
        for (int i = 0; i < 4; ++i)
            #pragma unroll
            for (int j = 0; j < 8; ++j) acc[i][j] = 0.0f;

        for (int m0 = 0; m0 < N_; m0 += 32) {
            __syncthreads();   // prior-iter reads of Ps/Whs done; stats visible
            // compute P tile 64x32 (k = m-local, i = n-local)
            {
                int i = t >> 2;
                int kbase = (t & 3) * 8;
                float f1v = sf1[i], rmv = srm[i], inv = sinv[i];
                const int* adjrow = adj + ((size_t)b * N_ + (n0 + i)) * N_ + m0 + kbase;
                #pragma unroll
                for (int kk = 0; kk < 8; ++kk) {
                    int k = kbase + kk;
                    float e = f1v + __ldg(&f2h[m0 + k]);
                    e = e > 0.0f ? e : 0.2f * e;
                    float p = (adjrow[kk] > 0) ? __expf(e - rmv) * inv : 0.0f;
                    Ps[k][i] = p;
                }
            }
            // load Wh tile 32x128
            {
                int j = (t & 31) * 4;
                int k = t >> 5;
                #pragma unroll
                for (int p4 = 0; p4 < 4; ++p4, k += 8)
                    *(float4*)&Whs[k][j] =
                        *(const float4*)&Whh[(size_t)(m0 + k) * DOUT + f0 + j];
            }
            __syncthreads();
            #pragma unroll
            for (int k = 0; k < 32; ++k) {
                float rp[4];
                #pragma unroll
                for (int i = 0; i < 4; ++i) rp[i] = Ps[k][ty * 4 + i];
                float rw[8];
                *(float4*)&rw[0] = *(const float4*)&Whs[k][tx * 8];
                *(float4*)&rw[4] = *(const float4*)&Whs[k][tx * 8 + 4];
                #pragma unroll
                for (int i = 0; i < 4; ++i)
                    #pragma unroll
                    for (int j = 0; j < 8; ++j)
                        acc[i][j] = fmaf(rp[i], rw[j], acc[i][j]);
            }
        }
        // head epilogue
        if (FINAL) {
            #pragma unroll
            for (int i = 0; i < 4; ++i)
                #pragma unroll
                for (int j = 0; j < 8; ++j) sum[i][j] = acc[i][j];
        } else {
            #pragma unroll
            for (int i = 0; i < 4; ++i)
                #pragma unroll
                for (int j = 0; j < 8; ++j) {
                    float v = acc[i][j];
                    sum[i][j] += (v > 0.0f) ? v : expm1f(v);   // ELU
                }
        }
    }

    #pragma unroll
    for (int i = 0; i < 4; ++i) {
        float r[8];
        #pragma unroll
        for (int j = 0; j < 8; ++j) {
            float v = sum[i][j];
            r[j] = FINAL ? fmaxf(v, 0.0f) : v * (1.0f / (float)H_);
        }
        size_t off = ((size_t)b * N_ + n0 + ty * 4 + i) * DOUT + f0 + tx * 8;
        *(float4*)&out[off]     = *(float4*)&r[0];
        *(float4*)&out[off + 4] = *(float4*)&r[4];
    }
}

// ---------------- launch --------------------------------------------------
extern "C" void kernel_launch(void* const* d_in, const int* in_sizes, int n_in,
                              void* d_out, int out_size)
{
    const float* x    = (const float*)d_in[0];
    const int*   adj  = (const int*)  d_in[1];
    const float* W0   = (const float*)d_in[2];
    const float* a1_0 = (const float*)d_in[3];
    const float* a2_0 = (const float*)d_in[4];
    const float* Wo   = (const float*)d_in[5];
    const float* a1_o = (const float*)d_in[6];
    const float* a2_o = (const float*)d_in[7];
    float* out = (float*)d_out;

    float *Wh, *f1, *f2, *rm, *dn, *hmid, *Wh2, *f1b, *f2b, *rm2, *dn2;
    cudaGetSymbolAddress((void**)&Wh,   g_Wh);
    cudaGetSymbolAddress((void**)&f1,   g_f1);
    cudaGetSymbolAddress((void**)&f2,   g_f2);
    cudaGetSymbolAddress((void**)&rm,   g_rm);
    cudaGetSymbolAddress((void**)&dn,   g_dn);
    cudaGetSymbolAddress((void**)&hmid, g_hmid);
    cudaGetSymbolAddress((void**)&Wh2,  g_Wh2);
    cudaGetSymbolAddress((void**)&f1b,  g_f1b);
    cudaGetSymbolAddress((void**)&f2b,  g_f2b);
    cudaGetSymbolAddress((void**)&rm2,  g_rm2);
    cudaGetSymbolAddress((void**)&dn2,  g_dn2);

    // ---- layer 1 (8 heads) ----
    sgemm_kernel<<<dim3(M_ / 128, DOUT / 128, H_), 256>>>(x, W0, Wh, M_, DIN, DOUT);
    f12_kernel<<<(H_ * M_) / 8, 256>>>(Wh, a1_0, a2_0, f1, f2, H_ * M_, M_);
    rowstats_kernel<<<(H_ * M_) / 8, 256>>>(f1, f2, adj, rm, dn, H_ * M_);
    attn_kernel<H_, false><<<dim3(DOUT / 128, N_ / 64, B_), 256>>>(
        Wh, f1, f2, rm, dn, adj, hmid);

    // ---- layer 2 (single head, ReLU) ----
    sgemm_kernel<<<dim3(M_ / 128, DOUT / 128, 1), 256>>>(hmid, Wo, Wh2, M_, DOUT, DOUT);
    f12_kernel<<<M_ / 8, 256>>>(Wh2, a1_o, a2_o, f1b, f2b, M_, M_);
    rowstats_kernel<<<M_ / 8, 256>>>(f1b, f2b, adj, rm2, dn2, M_);
    attn_kernel<1, true><<<dim3(DOUT / 128, N_ / 64, B_), 256>>>(
        Wh2, f1b, f2b, rm2, dn2, adj, out);
}

// round 4
// speedup vs baseline: 2.3540x; 2.3540x over previous
#include <cuda_runtime.h>
#include <cuda_fp16.h>
#include <math.h>
#include <stdint.h>

#define B_  32
#define N_  512
#define DIN 768
#define DOUT 256
#define H_  8
#define M_  (B_ * N_)

// ---------------- device scratch ----------------
__device__ __half g_xh [(size_t)M_ * DIN];
__device__ __half g_xl [(size_t)M_ * DIN];
__device__ __half g_w0h[(size_t)H_ * DOUT * DIN];  // [h][n][k]
__device__ __half g_w0l[(size_t)H_ * DOUT * DIN];
__device__ __half g_Whh[(size_t)H_ * M_ * DOUT];
__device__ __half g_Whl[(size_t)H_ * M_ * DOUT];
__device__ float  g_f1 [H_ * M_];
__device__ float  g_f2 [H_ * M_];
__device__ float  g_rm [H_ * M_];
__device__ float  g_dn [H_ * M_];
__device__ __half g_hmh[(size_t)M_ * DOUT];
__device__ __half g_hml[(size_t)M_ * DOUT];
__device__ __half g_woh[(size_t)DOUT * DOUT];
__device__ __half g_wol[(size_t)DOUT * DOUT];
__device__ __half g_W2h[(size_t)M_ * DOUT];
__device__ __half g_W2l[(size_t)M_ * DOUT];
__device__ float  g_f1b[M_];
__device__ float  g_f2b[M_];
__device__ float  g_rm2[M_];
__device__ float  g_dn2[M_];

// ---------------- PTX helpers (compute_103-safe: no tcgen05) ----------------
__device__ __forceinline__ uint32_t smem_u32(const void* p) {
    uint32_t a;
    asm("{ .reg .u64 t; cvta.to.shared.u64 t, %1; cvt.u32.u64 %0, t; }" : "=r"(a) : "l"(p));
    return a;
}
__device__ __forceinline__ void cp16(uint32_t d, const void* s) {
    asm volatile("cp.async.cg.shared.global [%0], [%1], 16;" :: "r"(d), "l"(s));
}
#define CP_COMMIT() asm volatile("cp.async.commit_group;")
#define CP_WAIT(n)  asm volatile("cp.async.wait_group %0;" :: "n"(n))

#define LDM_X4(r, addr) \
    asm volatile("ldmatrix.sync.aligned.m8n8.x4.shared.b16 {%0,%1,%2,%3}, [%4];" \
        : "=r"((r)[0]), "=r"((r)[1]), "=r"((r)[2]), "=r"((r)[3]) : "r"(addr))
#define LDM_X2(r, addr) \
    asm volatile("ldmatrix.sync.aligned.m8n8.x2.shared.b16 {%0,%1}, [%2];" \
        : "=r"((r)[0]), "=r"((r)[1]) : "r"(addr))
#define LDM_X2T(r, addr) \
    asm volatile("ldmatrix.sync.aligned.m8n8.x2.trans.shared.b16 {%0,%1}, [%2];" \
        : "=r"((r)[0]), "=r"((r)[1]) : "r"(addr))

__device__ __forceinline__ void mma_f16(float* c, const uint32_t* a, const uint32_t* b) {
    asm volatile("mma.sync.aligned.m16n8k16.row.col.f32.f16.f16.f32 "
        "{%0,%1,%2,%3}, {%4,%5,%6,%7}, {%8,%9}, {%0,%1,%2,%3};"
        : "+f"(c[0]), "+f"(c[1]), "+f"(c[2]), "+f"(c[3])
        : "r"(a[0]), "r"(a[1]), "r"(a[2]), "r"(a[3]), "r"(b[0]), "r"(b[1]));
}

// ---------------- conversion kernels ----------------
__global__ __launch_bounds__(256) void split_kernel(
    const float* __restrict__ src, __half* __restrict__ hi,
    __half* __restrict__ lo, int n4)
{
    int i = blockIdx.x * 256 + threadIdx.x;
    if (i >= n4) return;
    float4 v = ((const float4*)src)[i];
    __half h0 = __float2half(v.x), h1 = __float2half(v.y);
    __half h2 = __float2half(v.z), h3 = __float2half(v.w);
    __half2 hA = __halves2half2(h0, h1), hB = __halves2half2(h2, h3);
    __half2 lA = __halves2half2(__float2half(v.x - __half2float(h0)),
                                __float2half(v.y - __half2float(h1)));
    __half2 lB = __halves2half2(__float2half(v.z - __half2float(h2)),
                                __float2half(v.w - __half2float(h3)));
    ((__half2*)hi)[2 * i] = hA; ((__half2*)hi)[2 * i + 1] = hB;
    ((__half2*)lo)[2 * i] = lA; ((__half2*)lo)[2 * i + 1] = lB;
}

// W: [z][K][N] fp32 -> [z][N][K] fp16 hi/lo
__global__ __launch_bounds__(256) void wsplit_kernel(
    const float* __restrict__ W, __half* __restrict__ bh,
    __half* __restrict__ bl, int Kd, int Nd)
{
    int z = blockIdx.z;
    int i = blockIdx.x * 256 + threadIdx.x;
    if (i >= Kd * Nd) return;
    int n = i / Kd, k = i % Kd;
    float v = W[(size_t)z * Kd * Nd + (size_t)k * Nd + n];
    __half h = __float2half(v);
    bh[(size_t)z * Kd * Nd + i] = h;
    bl[(size_t)z * Kd * Nd + i] = __float2half(v - __half2float(h));
}

// ================= HMMA split GEMM: C[z] = A @ B[z]^T =================
// A: [M][K] hi/lo, B: [z][Nt][K] hi/lo, C: [z][M][Nt] hi/lo fp16.
// CTA 128x128, K-chunk 32, 8 warps (2m x 4n), warp 64x32.
// smem stage: 4 tiles [128][40] half; tile 10240B, stage 40960B.
#define GEMM_SMEM (2 * 40960)

__global__ __launch_bounds__(256, 1) void gemm_mma_kernel(
    const __half* __restrict__ Ah, const __half* __restrict__ Al,
    const __half* __restrict__ Bh, const __half* __restrict__ Bl,
    __half* __restrict__ Chh, __half* __restrict__ Chl, int K, int Nt)
{
    extern __shared__ __align__(128) char sm[];
    const uint32_t sb = smem_u32(sm);
    const int t = threadIdx.x, lane = t & 31, wid = t >> 5;
    const int m0 = blockIdx.x * 128, f0 = blockIdx.y * 128, z = blockIdx.z;
    const int warp_m = wid & 1, warp_n = wid >> 1;

    const __half* As_h = Ah + (size_t)m0 * K;
    const __half* As_l = Al + (size_t)m0 * K;
    const __half* Bs_h = Bh + (size_t)z * Nt * K + (size_t)f0 * K;
    const __half* Bs_l = Bl + (size_t)z * Nt * K + (size_t)f0 * K;
    __half* Ch = Chh + (size_t)z * M_ * Nt;
    __half* Cl = Chl + (size_t)z * M_ * Nt;

    float acc[4][4][4];
    #pragma unroll
    for (int a = 0; a < 4; ++a)
        #pragma unroll
        for (int b = 0; b < 4; ++b)
            #pragma unroll
            for (int c = 0; c < 4; ++c) acc[a][b][c] = 0.0f;

    const int row = t >> 1, half = t & 1;
    auto prefetch = [&](int c, int s) {
        const int kc = c * 32;
        const __half* srcs[4] = { As_h + kc, As_l + kc, Bs_h + kc, Bs_l + kc };
        #pragma unroll
        for (int tile = 0; tile < 4; ++tile) {
            uint32_t dst = sb + s * 40960 + tile * 10240 + row * 80 + half * 32;
            const __half* src = srcs[tile] + (size_t)row * K + half * 16;
            cp16(dst, src);
            cp16(dst + 16, src + 8);
        }
        CP_COMMIT();
    };

    const int NC = K >> 5;
    prefetch(0, 0);
    for (int c = 0; c < NC; ++c) {
        const int s = c & 1;
        if (c + 1 < NC) { prefetch(c + 1, s ^ 1); CP_WAIT(1); }
        else CP_WAIT(0);
        __syncthreads();

        const uint32_t bAh = sb + s * 40960;
        const uint32_t bAl = bAh + 10240;
        const uint32_t bBh = bAh + 20480;
        const uint32_t bBl = bAh + 30720;
        #pragma unroll
        for (int k16 = 0; k16 < 2; ++k16) {
            const int kc = k16 * 16;
            uint32_t ah[4][4], al[4][4];
            #pragma unroll
            for (int mf = 0; mf < 4; ++mf) {
                uint32_t off = (uint32_t)((warp_m * 64 + mf * 16 + (lane & 15)) * 80
                                          + (kc + ((lane >> 4) << 3)) * 2);
                LDM_X4(ah[mf], bAh + off);
                LDM_X4(al[mf], bAl + off);
            }
            #pragma unroll
            for (int nf = 0; nf < 4; ++nf) {
                uint32_t boff = (uint32_t)((warp_n * 32 + nf * 8 + (lane & 7)) * 80
                                           + (kc + (((lane >> 3) & 1) << 3)) * 2);
                uint32_t bh[2], bl[2];
                LDM_X2(bh, bBh + boff);
                LDM_X2(bl, bBl + boff);
                #pragma unroll
                for (int mf = 0; mf < 4; ++mf) {
                    mma_f16(acc[mf][nf], ah[mf], bh);
                    mma_f16(acc[mf][nf], ah[mf], bl);
                    mma_f16(acc[mf][nf], al[mf], bh);
                }
            }
        }
        __syncthreads();
    }

    // epilogue: write hi/lo fp16
    #pragma unroll
    for (int mf = 0; mf < 4; ++mf)
        #pragma unroll
        for (int nf = 0; nf < 4; ++nf) {
            int r0 = m0 + warp_m * 64 + mf * 16 + (lane >> 2);
            int col = f0 + warp_n * 32 + nf * 8 + (lane & 3) * 2;
            #pragma unroll
            for (int hh = 0; hh < 2; ++hh) {
                float c0 = acc[mf][nf][hh * 2], c1 = acc[mf][nf][hh * 2 + 1];
                int r = r0 + hh * 8;
                __half h0 = __float2half(c0), h1 = __float2half(c1);
                *(__half2*)(Ch + (size_t)r * Nt + col) = __halves2half2(h0, h1);
                *(__half2*)(Cl + (size_t)r * Nt + col) = __halves2half2(
                    __float2half(c0 - __half2float(h0)),
                    __float2half(c1 - __half2float(h1)));
            }
        }
}

// ---------------- f1/f2 from hi/lo halves ----------------
__global__ __launch_bounds__(256) void f12_kernel(
    const __half* __restrict__ Whh, const __half* __restrict__ Whl,
    const float* __restrict__ a1, const float* __restrict__ a2,
    float* __restrict__ f1, float* __restrict__ f2, int rows, int Mper)
{
    int warp = (blockIdx.x * blockDim.x + threadIdx.x) >> 5;
    int lane = threadIdx.x & 31;
    if (warp >= rows) return;
    int h = warp / Mper;
    const __half* rh = Whh + (size_t)warp * DOUT;
    const __half* rl = Whl + (size_t)warp * DOUT;
    const float* a1h = a1 + h * DOUT;
    const float* a2h = a2 + h * DOUT;
    float s1 = 0.0f, s2 = 0.0f;
    #pragma unroll
    for (int f = lane; f < DOUT; f += 32) {
        float v = __half2float(rh[f]) + __half2float(rl[f]);
        s1 = fmaf(v, a1h[f], s1);
        s2 = fmaf(v, a2h[f], s2);
    }
    #pragma unroll
    for (int off = 16; off; off >>= 1) {
        s1 += __shfl_xor_sync(0xffffffffu, s1, off);
        s2 += __shfl_xor_sync(0xffffffffu, s2, off);
    }
    if (lane == 0) { f1[warp] = s1; f2[warp] = s2; }
}

// ---------------- row stats ----------------
__global__ __launch_bounds__(256) void rowstats_kernel(
    const float* __restrict__ f1, const float* __restrict__ f2,
    const int* __restrict__ adj, float* __restrict__ rowmax,
    float* __restrict__ denom, int rows)
{
    int warp = (blockIdx.x * blockDim.x + threadIdx.x) >> 5;
    int lane = threadIdx.x & 31;
    if (warp >= rows) return;
    int n  = warp & (N_ - 1);
    int hb = warp >> 9;
    int b  = hb & (B_ - 1);
    float f1v = f1[warp];
    const float* f2row = f2 + (size_t)hb * N_;
    const int* adjrow  = adj + ((size_t)b * N_ + n) * N_;

    float e[16];
    float mx = -1e30f;
    #pragma unroll
    for (int q = 0; q < 16; ++q) {
        int m = q * 32 + lane;
        float v = f1v + f2row[m];
        v = v > 0.0f ? v : 0.2f * v;
        e[q] = (adjrow[m] > 0) ? v : -1e30f;
        mx = fmaxf(mx, e[q]);
    }
    #pragma unroll
    for (int off = 16; off; off >>= 1)
        mx = fmaxf(mx, __shfl_xor_sync(0xffffffffu, mx, off));
    float s = 0.0f;
    #pragma unroll
    for (int q = 0; q < 16; ++q)
        if (e[q] > -1e29f) s += __expf(e[q] - mx);
    #pragma unroll
    for (int off = 16; off; off >>= 1)
        s += __shfl_xor_sync(0xffffffffu, s, off);
    if (lane == 0) { rowmax[warp] = mx; denom[warp] = s; }
}

// ================= HMMA attention aggregation =================
// CTA: 64 n-rows x 256 f. 512 threads, 16 warps (2n x 8f), warp 32n x 32f.
// P (A operand) computed on the fly in fp32, split hi/lo into smem.
// Wh (B operand) streamed hi/lo via cp.async, ldmatrix.x2.trans.
// smem: stats 1024 | Ps [2 st][2 hl][64][40] = 20480 | Whs [2 st][2 hl][32][264] = 67584
#define ATTN_SMEM (1024 + 20480 + 67584)

template<int NHEADS, bool FINAL>
__global__ __launch_bounds__(512, 1) void attn_mma_kernel(
    const __half* __restrict__ Whh, const __half* __restrict__ Whl,
    const float* __restrict__ f1, const float* __restrict__ f2,
    const float* __restrict__ rowmax, const float* __restrict__ denom,
    const int* __restrict__ adj,
    __half* __restrict__ outh, __half* __restrict__ outl,
    float* __restrict__ outf)
{
    extern __shared__ __align__(128) char sm[];
    const uint32_t sb = smem_u32(sm);
    float* sf1  = (float*)sm;
    float* srm  = (float*)(sm + 256);
    float* sinv = (float*)(sm + 512);
    const uint32_t smP = sb + 1024;           // [st][hl][64][40]
    const uint32_t smW = sb + 1024 + 20480;   // [st][hl][32][264]

    const int t = threadIdx.x, lane = t & 31, wid = t >> 5;
    const int n0 = blockIdx.x * 64;
    const int b  = blockIdx.y;
    const int warp_n = wid & 1, warp_f = wid >> 1;

    float sum[2][4][4];
    #pragma unroll
    for (int a = 0; a < 2; ++a)
        #pragma unroll
        for (int c = 0; c < 4; ++c)
            #pragma unroll
            for (int d = 0; d < 4; ++d) sum[a][c][d] = 0.0f;

    const int pi  = t >> 3;          // 0..63 (n-local)
    const int pkb = (t & 3) * 8;     // unused
    (void)pkb;
    const int pk4 = (t & 7) * 4;     // 0..28 (m-local, 4 vals)
    const int wrow = (t & 255) >> 3; // Wh row 0..31
    const int wseg = t & 7;
    const int whl  = t >> 8;         // 0 or 1

    for (int h = 0; h < NHEADS; ++h) {
        const size_t hb = (size_t)h * B_ + b;
        const float* f2h = f2 + hb * N_;
        const __half* Wsh = Whh + hb * (size_t)N_ * DOUT;
        const __half* Wsl = Whl + hb * (size_t)N_ * DOUT;

        __syncthreads();
        if (t < 64) {
            sf1[t] = f1[hb * N_ + n0 + t];
            srm[t] = rowmax[hb * N_ + n0 + t];
            float d = denom[hb * N_ + n0 + t];
            sinv[t] = d > 0.0f ? 1.0f / d : 0.0f;
        }
        __syncthreads();

        float acc[2][4][4];
        #pragma unroll
        for (int a = 0; a < 2; ++a)
            #pragma unroll
            for (int c = 0; c < 4; ++c)
                #pragma unroll
                for (int d = 0; d < 4; ++d) acc[a][c][d] = 0.0f;

        auto computeP = [&](int c, int st) {
            const int m0 = c * 32;
            float f1v = sf1[pi], rmv = srm[pi], inv = sinv[pi];
            const int* adjrow = adj + ((size_t)b * N_ + n0 + pi) * N_ + m0 + pk4;
            int4 av = *(const int4*)adjrow;
            int am[4] = { av.x, av.y, av.z, av.w };
            __half hs[4], ls[4];
            #pragma unroll
            for (int kk = 0; kk < 4; ++kk) {
                float e = f1v + __ldg(&f2h[m0 + pk4 + kk]);
                e = e > 0.0f ? e : 0.2f * e;
                float p = (am[kk] > 0) ? __expf(e - rmv) * inv : 0.0f;
                hs[kk] = __float2half(p);
                ls[kk] = __float2half(p - __half2float(hs[kk]));
            }
            char* dh = sm + 1024 + st * 10240 + pi * 80 + pk4 * 2;
            char* dl = dh + 5120;
            ((__half2*)dh)[0] = __halves2half2(hs[0], hs[1]);
            ((__half2*)dh)[1] = __halves2half2(hs[2], hs[3]);
            ((__half2*)dl)[0] = __halves2half2(ls[0], ls[1]);
            ((__half2*)dl)[1] = __halves2half2(ls[2], ls[3]);
        };
        auto prefetchW = [&](int c, int st) {
            const int m0 = c * 32;
            const __half* src = (whl ? Wsl : Wsh) + (size_t)(m0 + wrow) * DOUT;
            uint32_t dst = smW + st * 33792 + whl * 16896 + wrow * 528;
            #pragma unroll
            for (int j = 0; j < 4; ++j) {
                int s8 = wseg + j * 8;
                cp16(dst + s8 * 16, src + s8 * 8);
            }
            CP_COMMIT();
        };

        computeP(0, 0);
        prefetchW(0, 0);
        for (int c = 0; c < 16; ++c) {
            const int st = c & 1;
            if (c < 15) {
                prefetchW(c + 1, st ^ 1);
                computeP(c + 1, st ^ 1);
                CP_WAIT(1);
            } else CP_WAIT(0);
            __syncthreads();

            const uint32_t Ph = smP + st * 10240;
            const uint32_t Pl = Ph + 5120;
            const uint32_t Wh_ = smW + st * 33792;
            const uint32_t Wl_ = Wh_ + 16896;
            #pragma unroll
            for (int k16 = 0; k16 < 2; ++k16) {
                const int kc = k16 * 16;
                uint32_t ah[2][4], al[2][4];
                #pragma unroll
                for (int mf = 0; mf < 2; ++mf) {
                    uint32_t off = (uint32_t)((warp_n * 32 + mf * 16 + (lane & 15)) * 80
                                              + (kc + ((lane >> 4) << 3)) * 2);
                    LDM_X4(ah[mf], Ph + off);
                    LDM_X4(al[mf], Pl + off);
                }
                #pragma unroll
                for (int nf = 0; nf < 4; ++nf) {
                    uint32_t woff = (uint32_t)((kc + (lane & 15)) * 528
                                               + (warp_f * 32 + nf * 8) * 2);
                    uint32_t bh[2], bl[2];
                    LDM_X2T(bh, Wh_ + woff);
                    LDM_X2T(bl, Wl_ + woff);
                    #pragma unroll
                    for (int mf = 0; mf < 2; ++mf) {
                        mma_f16(acc[mf][nf], ah[mf], bh);
                        mma_f16(acc[mf][nf], ah[mf], bl);
                        mma_f16(acc[mf][nf], al[mf], bh);
                    }
                }
            }
            __syncthreads();
        }

        if (FINAL) {
            #pragma unroll
            for (int a = 0; a < 2; ++a)
                #pragma unroll
                for (int c = 0; c < 4; ++c)
                    #pragma unroll
                    for (int d = 0; d < 4; ++d) sum[a][c][d] = acc[a][c][d];
        } else {
            #pragma unroll
            for (int a = 0; a < 2; ++a)
                #pragma unroll
                for (int c = 0; c < 4; ++c)
                    #pragma unroll
                    for (int d = 0; d < 4; ++d) {
                        float v = acc[a][c][d];
                        sum[a][c][d] += (v > 0.0f) ? v : expm1f(v);
                    }
        }
    }

    // write output
    #pragma unroll
    for (int mf = 0; mf < 2; ++mf)
        #pragma unroll
        for (int nf = 0; nf < 4; ++nf) {
            int r0  = n0 + warp_n * 32 + mf * 16 + (lane >> 2);
            int col = warp_f * 32 + nf * 8 + (lane & 3) * 2;
            #pragma unroll
            for (int hh = 0; hh < 2; ++hh) {
                int r = r0 + hh * 8;
                float c0 = sum[mf][nf][hh * 2], c1 = sum[mf][nf][hh * 2 + 1];
                if (FINAL) {
                    float2 v = { fmaxf(c0, 0.0f), fmaxf(c1, 0.0f) };
                    *(float2*)(outf + ((size_t)b * N_ + r) * DOUT + col) = v;
                } else {
                    c0 *= 0.125f; c1 *= 0.125f;
                    __half h0 = __float2half(c0), h1 = __float2half(c1);
                    *(__half2*)(outh + ((size_t)b * N_ + r) * DOUT + col) =
                        __halves2half2(h0, h1);
                    *(__half2*)(outl + ((size_t)b * N_ + r) * DOUT + col) =
                        __halves2half2(__float2half(c0 - __half2float(h0)),
                                       __float2half(c1 - __half2float(h1)));
                }
            }
        }
}

// ---------------- launch ----------------
extern "C" void kernel_launch(void* const* d_in, const int* in_sizes, int n_in,
                              void* d_out, int out_size)
{
    const float* x    = (const float*)d_in[0];
    const int*   adj  = (const int*)  d_in[1];
    const float* W0   = (const float*)d_in[2];
    const float* a1_0 = (const float*)d_in[3];
    const float* a2_0 = (const float*)d_in[4];
    const float* Wo   = (const float*)d_in[5];
    const float* a1_o = (const float*)d_in[6];
    const float* a2_o = (const float*)d_in[7];
    float* out = (float*)d_out;

    __half *xh, *xl, *w0h, *w0l, *Whh, *Whl, *hmh, *hml, *woh, *wol, *W2h, *W2l;
    float *f1, *f2, *rm, *dn, *f1b, *f2b, *rm2, *dn2;
    cudaGetSymbolAddress((void**)&xh,  g_xh);
    cudaGetSymbolAddress((void**)&xl,  g_xl);
    cudaGetSymbolAddress((void**)&w0h, g_w0h);
    cudaGetSymbolAddress((void**)&w0l, g_w0l);
    cudaGetSymbolAddress((void**)&Whh, g_Whh);
    cudaGetSymbolAddress((void**)&Whl, g_Whl);
    cudaGetSymbolAddress((void**)&f1,  g_f1);
    cudaGetSymbolAddress((void**)&f2,  g_f2);
    cudaGetSymbolAddress((void**)&rm,  g_rm);
    cudaGetSymbolAddress((void**)&dn,  g_dn);
    cudaGetSymbolAddress((void**)&hmh, g_hmh);
    cudaGetSymbolAddress((void**)&hml, g_hml);
    cudaGetSymbolAddress((void**)&woh, g_woh);
    cudaGetSymbolAddress((void**)&wol, g_wol);
    cudaGetSymbolAddress((void**)&W2h, g_W2h);
    cudaGetSymbolAddress((void**)&W2l, g_W2l);
    cudaGetSymbolAddress((void**)&f1b, g_f1b);
    cudaGetSymbolAddress((void**)&f2b, g_f2b);
    cudaGetSymbolAddress((void**)&rm2, g_rm2);
    cudaGetSymbolAddress((void**)&dn2, g_dn2);

    cudaFuncSetAttribute(gemm_mma_kernel,
        cudaFuncAttributeMaxDynamicSharedMemorySize, GEMM_SMEM);
    cudaFuncSetAttribute(attn_mma_kernel<H_, false>,
        cudaFuncAttributeMaxDynamicSharedMemorySize, ATTN_SMEM);
    cudaFuncSetAttribute(attn_mma_kernel<1, true>,
        cudaFuncAttributeMaxDynamicSharedMemorySize, ATTN_SMEM);

    // ---- layer 1 ----
    split_kernel<<<(M_ * DIN / 4 + 255) / 256, 256>>>(x, xh, xl, M_ * DIN / 4);
    wsplit_kernel<<<dim3((DIN * DOUT + 255) / 256, 1, H_), 256>>>(W0, w0h, w0l, DIN, DOUT);
    gemm_mma_kernel<<<dim3(M_ / 128, DOUT / 128, H_), 256, GEMM_SMEM>>>(
        xh, xl, w0h, w0l, Whh, Whl, DIN, DOUT);
    f12_kernel<<<(H_ * M_) / 8, 256>>>(Whh, Whl, a1_0, a2_0, f1, f2, H_ * M_, M_);
    rowstats_kernel<<<(H_ * M_) / 8, 256>>>(f1, f2, adj, rm, dn, H_ * M_);
    attn_mma_kernel<H_, false><<<dim3(N_ / 64, B_), 512, ATTN_SMEM>>>(
        Whh, Whl, f1, f2, rm, dn, adj, hmh, hml, nullptr);

    // ---- layer 2 ----
    wsplit_kernel<<<dim3((DOUT * DOUT + 255) / 256, 1, 1), 256>>>(Wo, woh, wol, DOUT, DOUT);
    gemm_mma_kernel<<<dim3(M_ / 128, DOUT / 128, 1), 256, GEMM_SMEM>>>(
        hmh, hml, woh, wol, W2h, W2l, DOUT, DOUT);
    f12_kernel<<<M_ / 8, 256>>>(W2h, W2l, a1_o, a2_o, f1b, f2b, M_, M_);
    rowstats_kernel<<<M_ / 8, 256>>>(f1b, f2b, adj, rm2, dn2, M_);
    attn_mma_kernel<1, true><<<dim3(N_ / 64, B_), 512, ATTN_SMEM>>>(
        W2h, W2l, f1b, f2b, rm2, dn2, adj, nullptr, nullptr, out);
}